// round 13
// baseline (speedup 1.0000x reference)
#include <cuda_runtime.h>
#include <cuda_fp16.h>
#include <math.h>
#include <stdint.h>

// ---------------------------------------------------------------------------
// Problem constants
// ---------------------------------------------------------------------------
#define T_TOK 4096
#define D_DIM 1024
#define F_DIM 4096
#define E_NUM 8
#define K_TOP 2

#define BM 128
#define BN 128
#define BK 32
#define NSTAGE 5

#define CAPR (T_TOK * K_TOP + E_NUM * BM)   // 9216
#define ROWTILES (CAPR / BM)                // 72

// prep work partition (flat 1D grid)
#define P_ROUTER 512
#define P_W1CONV 1536
#define P_ZERO   128
#define P_TOTAL  (P_ROUTER + P_W1CONV + P_ZERO + 1)   // 2177

// SMEM stage layout (bytes, within one stage)
#define A_ROWB 80                            // 32 fp16 = 64B + 16B pad
#define SM_A    0
#define SM_B    (BM * A_ROWB)                // 10240
#define STAGEB  (SM_B + BK * 256)            // 18432
#define SM_TOTAL (STAGEB * NSTAGE)           // 92160  (x2 CTAs = 180KB < 228KB)

// ---------------------------------------------------------------------------
// PTX helpers
// ---------------------------------------------------------------------------
static __device__ __forceinline__ uint32_t smem_u32(const void* p) {
    uint32_t a;
    asm("{ .reg .u64 t; cvta.to.shared.u64 t, %1; cvt.u32.u64 %0, t; }" : "=r"(a) : "l"(p));
    return a;
}

#define CP16(dst, src) \
    asm volatile("cp.async.cg.shared.global [%0], [%1], 16;" :: "r"(dst), "l"(src))
#define CP_COMMIT() asm volatile("cp.async.commit_group;")
#define CP_WAIT3()  asm volatile("cp.async.wait_group 3;")

#define LDSMX4(R, addr) \
    asm volatile("ldmatrix.sync.aligned.m8n8.x4.shared.b16 {%0,%1,%2,%3}, [%4];" \
        : "=r"((R)[0]), "=r"((R)[1]), "=r"((R)[2]), "=r"((R)[3]) : "r"(addr))
#define LDSMX4T(R, addr) \
    asm volatile("ldmatrix.sync.aligned.m8n8.x4.trans.shared.b16 {%0,%1,%2,%3}, [%4];" \
        : "=r"((R)[0]), "=r"((R)[1]), "=r"((R)[2]), "=r"((R)[3]) : "r"(addr))

#define MMA16816(C, A, B) \
    asm volatile("mma.sync.aligned.m16n8k16.row.col.f32.f16.f16.f32 " \
        "{%0,%1,%2,%3}, {%4,%5,%6,%7}, {%8,%9}, {%0,%1,%2,%3};" \
        : "+f"((C)[0]), "+f"((C)[1]), "+f"((C)[2]), "+f"((C)[3]) \
        : "r"((A)[0]), "r"((A)[1]), "r"((A)[2]), "r"((A)[3]), "r"((B)[0]), "r"((B)[1]))

#define REDADD2(addr, v0, v1) \
    asm volatile("red.global.add.v2.f32 [%0], {%1, %2};" :: "l"(addr), "f"(v0), "f"(v1) : "memory")

static __device__ __forceinline__ uint32_t pack_h2(__half a, __half b) {
    return ((uint32_t)__half_as_ushort(b) << 16) | (uint32_t)__half_as_ushort(a);
}

static __device__ __forceinline__ uint32_t ld_acq(const uint32_t* p) {
    uint32_t v;
    asm volatile("ld.global.acquire.gpu.u32 %0, [%1];" : "=r"(v) : "l"(p));
    return v;
}

// ---------------------------------------------------------------------------
// Scratch (static device globals)
// ---------------------------------------------------------------------------
__device__ __align__(16) __half g_xf[(size_t)T_TOK * D_DIM];
__device__ __align__(16) __half g_w1f[(size_t)E_NUM * D_DIM * F_DIM];
__device__ __align__(16) __half g_w2f[(size_t)E_NUM * F_DIM * D_DIM];
__device__ __align__(16) __half g_Hf[(size_t)CAPR * F_DIM];
__device__ int   g_rowtok[CAPR];
__device__ float g_roww[CAPR];
__device__ float g_tokw[T_TOK * K_TOP];
__device__ int   g_toke[T_TOK * K_TOP];
__device__ int   g_poff[E_NUM + 1];
__device__ int   g_npad;
__device__ uint32_t g_rtdone = 0;   // router-done counter (self-resetting)

// ---------------------------------------------------------------------------
// Fused prep kernel (flat grid, work-proportional partition):
//   [0, P_ROUTER)           router (1 warp/token) + writes g_xf as byproduct
//   [.., +P_W1CONV)         w1 -> fp16, 8 floats/thread/iter
//   [.., +P_ZERO)           zero out[]
//   last CTA                gated scatter (count -> offsets -> place)
// ---------------------------------------------------------------------------
__global__ void __launch_bounds__(256)
prep_kernel(const float* __restrict__ x,
            const float* __restrict__ rw,
            const float* __restrict__ rb,
            const float4* __restrict__ w1,
            float* __restrict__ out) {
    int cta = blockIdx.x;
    int tid = threadIdx.x;

    if (cta < P_ROUTER) {
        // ---- router + x->fp16 ----
        int warp = cta * 8 + (tid >> 5);
        int lane = tid & 31;
        const float* xr = x + (size_t)warp * D_DIM;
        uint32_t* xo = (uint32_t*)(g_xf + (size_t)warp * D_DIM);
        float acc[E_NUM];
#pragma unroll
        for (int e = 0; e < E_NUM; e++) acc[e] = 0.0f;
        for (int d = lane * 2; d < D_DIM; d += 64) {
            float v0 = xr[d];
            float v1 = xr[d + 1];
            const float* w0 = rw + (size_t)d * E_NUM;
            const float* w1p = w0 + E_NUM;
#pragma unroll
            for (int e = 0; e < E_NUM; e++) acc[e] += v0 * w0[e] + v1 * w1p[e];
            xo[d >> 1] = pack_h2(__float2half_rn(v0), __float2half_rn(v1));
        }
#pragma unroll
        for (int off = 16; off; off >>= 1)
#pragma unroll
            for (int e = 0; e < E_NUM; e++)
                acc[e] += __shfl_down_sync(0xFFFFFFFFu, acc[e], off);
        if (lane == 0) {
            float l[E_NUM];
#pragma unroll
            for (int e = 0; e < E_NUM; e++) l[e] = acc[e] + rb[e];
            int i0 = 0;
#pragma unroll
            for (int e = 1; e < E_NUM; e++) if (l[e] > l[i0]) i0 = e;
            int i1 = -1;
#pragma unroll
            for (int e = 0; e < E_NUM; e++) {
                if (e == i0) continue;
                if (i1 < 0 || l[e] > l[i1]) i1 = e;
            }
            float w0 = 1.0f / (1.0f + expf(l[i1] - l[i0]));
            g_toke[warp * 2 + 0] = i0;
            g_toke[warp * 2 + 1] = i1;
            g_tokw[warp * 2 + 0] = w0;
            g_tokw[warp * 2 + 1] = 1.0f - w0;
        }
        __threadfence();
        __syncthreads();
        if (tid == 0) atomicAdd(&g_rtdone, 1u);
    } else if (cta < P_ROUTER + P_W1CONV) {
        // ---- w1 -> fp16, 8 floats per thread per iteration ----
        const int n8 = E_NUM * D_DIM * F_DIM / 8;
        int stride = P_W1CONV * 256;
        for (int i = (cta - P_ROUTER) * 256 + tid; i < n8; i += stride) {
            float4 a = w1[2 * i];
            float4 b = w1[2 * i + 1];
            uint4 o;
            o.x = pack_h2(__float2half_rn(a.x), __float2half_rn(a.y));
            o.y = pack_h2(__float2half_rn(a.z), __float2half_rn(a.w));
            o.z = pack_h2(__float2half_rn(b.x), __float2half_rn(b.y));
            o.w = pack_h2(__float2half_rn(b.z), __float2half_rn(b.w));
            ((uint4*)g_w1f)[i] = o;
        }
    } else if (cta < P_ROUTER + P_W1CONV + P_ZERO) {
        // ---- zero out[] ----
        float4* o4 = (float4*)out;
        const int n4 = T_TOK * D_DIM / 4;
        int stride = P_ZERO * 256;
        float4 z = make_float4(0.f, 0.f, 0.f, 0.f);
        for (int i = (cta - P_ROUTER - P_W1CONV) * 256 + tid; i < n4; i += stride)
            o4[i] = z;
    } else {
        // ---- gated scatter CTA ----
        __shared__ int s_cnt[E_NUM];
        __shared__ int s_cur[E_NUM];
        if (tid < E_NUM) s_cnt[tid] = 0;
        if (tid == 0) {
            while (ld_acq(&g_rtdone) < P_ROUTER) __nanosleep(128);
        }
        __syncthreads();
        for (int i = tid; i < T_TOK * K_TOP; i += 256)
            atomicAdd(&s_cnt[g_toke[i]], 1);
        __syncthreads();
        if (tid == 0) {
            int off = 0;
            for (int e = 0; e < E_NUM; e++) {
                g_poff[e] = off;
                s_cur[e] = off;
                off += ((s_cnt[e] + BM - 1) / BM) * BM;
            }
            g_poff[E_NUM] = off;
            g_npad = off;
        }
        __syncthreads();
        for (int i = tid; i < CAPR; i += 256) {
            g_rowtok[i] = 0;
            g_roww[i] = 0.0f;
        }
        __syncthreads();
        for (int i = tid; i < T_TOK * K_TOP; i += 256) {
            int e = g_toke[i];
            int p = atomicAdd(&s_cur[e], 1);
            g_rowtok[p] = i >> 1;
            g_roww[p] = g_tokw[i];
        }
        __syncthreads();
        if (tid == 0) g_rtdone = 0;   // self-reset for next graph replay
    }
}

// ---------------------------------------------------------------------------
// fp16 HMMA GEMM (single product), BK=32, 5-stage cp.async pipeline,
// one barrier per k-chunk, chunk-wide B-fragment preload (R10 body).
// GEMM1 (GATHER): blockIdx.y==0 slice converts w2->fp16; epilogue GELU->g_Hf.
// GEMM2 (!GATHER): epilogue w*(acc+bias) accumulated into out[] (red.v2.f32).
// ---------------------------------------------------------------------------
template<bool GATHER, int KTOT, int NTOT>
__global__ void __launch_bounds__(256, 2)
moe_gemm(const float* __restrict__ bias, float* __restrict__ out,
         const float4* __restrict__ cvt_src, __half* __restrict__ cvt_dst, int cvt_n4) {
    int by = blockIdx.y;
    if (GATHER) {
        if (by == 0) {
            int stride = gridDim.x * blockDim.x;
            int base = blockIdx.x * blockDim.x + threadIdx.x;
            for (int i = base; i < cvt_n4; i += 4 * stride) {
#pragma unroll
                for (int u = 0; u < 4; u++) {
                    int j = i + u * stride;
                    if (j < cvt_n4) {
                        float4 v = cvt_src[j];
                        uint32_t w0 = pack_h2(__float2half_rn(v.x), __float2half_rn(v.y));
                        uint32_t w1 = pack_h2(__float2half_rn(v.z), __float2half_rn(v.w));
                        ((uint2*)cvt_dst)[j] = make_uint2(w0, w1);
                    }
                }
            }
            return;
        }
        by -= 1;
    }

    int row0 = by * BM;
    if (row0 >= g_npad) return;
    int e = 0;
    while (row0 >= g_poff[e + 1]) e++;
    int n0 = blockIdx.x * BN;

    extern __shared__ char smem[];
    uint32_t su = smem_u32(smem);

    int tid = threadIdx.x;
    int lane = tid & 31;
    int wid = tid >> 5;
    int warp_m = wid & 1;
    int warp_n = wid >> 1;

    const __half* a_g;
    {
        int r = tid >> 1;
        if (GATHER) {
            int tok = g_rowtok[row0 + r];
            a_g = g_xf + (size_t)tok * KTOT;
        } else {
            a_g = g_Hf + (size_t)(row0 + r) * KTOT;
        }
    }
    const __half* b_g = (GATHER ? g_w1f : g_w2f) + (size_t)e * KTOT * NTOT;

    int ar = tid >> 1;
    int ac = (tid & 1) * 2;
    uint32_t a_dst = su + ar * A_ROWB + ac * 16;
    int bkr = tid >> 3;
    int bc = (tid & 7) * 2;
    uint32_t b_dst0 = su + SM_B + bkr * 256 + ((bc * 16) ^ ((bkr & 7) << 4));
    uint32_t b_dst1 = su + SM_B + bkr * 256 + (((bc + 1) * 16) ^ ((bkr & 7) << 4));

    float acc[4][4][4];
#pragma unroll
    for (int mt = 0; mt < 4; mt++)
#pragma unroll
        for (int nt = 0; nt < 4; nt++)
#pragma unroll
            for (int q = 0; q < 4; q++) acc[mt][nt][q] = 0.0f;

    uint32_t a_lds = (uint32_t)((warp_m * 64 + (lane & 15)) * A_ROWB + ((lane >> 4) * 8) * 2);
    int krow_base = (lane & 7) + ((lane >> 3) & 1) * 8;
    int nb_base = (warp_n * 32 + ((lane >> 4) & 1) * 8) * 2;

    const int NK = KTOT / BK;

#define ISSUE_COPY(kc, sb_off)                                                      \
    do {                                                                            \
        int k0_ = (kc) * BK;                                                        \
        const __half* pa_ = a_g + k0_ + ac * 8;                                     \
        CP16((sb_off) + a_dst, pa_); CP16((sb_off) + a_dst + 16, pa_ + 8);          \
        const __half* pb_ = b_g + (size_t)(k0_ + bkr) * NTOT + n0 + bc * 8;         \
        CP16((sb_off) + b_dst0, pb_); CP16((sb_off) + b_dst1, pb_ + 8);             \
    } while (0)

    ISSUE_COPY(0, 0);
    CP_COMMIT();
    ISSUE_COPY(1, STAGEB);
    CP_COMMIT();
    ISSUE_COPY(2, 2 * STAGEB);
    CP_COMMIT();
    ISSUE_COPY(3, 3 * STAGEB);
    CP_COMMIT();

    int stage = 0;
    int stage_w = 4;
    for (int kc = 0; kc < NK; kc++) {
        CP_WAIT3();
        __syncthreads();
        if (kc + 4 < NK) ISSUE_COPY(kc + 4, (uint32_t)stage_w * STAGEB);
        CP_COMMIT();

        uint32_t sb = su + (uint32_t)stage * STAGEB;

        uint32_t b_r[2][4][2];
#pragma unroll
        for (int ks = 0; ks < 2; ks++) {
#pragma unroll
            for (int pt = 0; pt < 2; pt++) {
                int krow = ks * 16 + krow_base;
                int nb = nb_base + pt * 32;
                uint32_t bd = sb + SM_B + krow * 256 + (nb ^ ((krow & 7) << 4));
                uint32_t r[4];
                LDSMX4T(r, bd);
                b_r[ks][2 * pt][0] = r[0]; b_r[ks][2 * pt][1] = r[1];
                b_r[ks][2 * pt + 1][0] = r[2]; b_r[ks][2 * pt + 1][1] = r[3];
            }
        }
#pragma unroll
        for (int ks = 0; ks < 2; ks++) {
            uint32_t a_r[4][4];
#pragma unroll
            for (int mt = 0; mt < 4; mt++) {
                uint32_t ad = sb + a_lds + (uint32_t)(mt * 16 * A_ROWB + ks * 32);
                LDSMX4(a_r[mt], ad);
            }
#pragma unroll
            for (int mt = 0; mt < 4; mt++)
#pragma unroll
                for (int nt = 0; nt < 4; nt++)
                    MMA16816(acc[mt][nt], a_r[mt], b_r[ks][nt]);
        }
        stage = (stage == NSTAGE - 1) ? 0 : stage + 1;
        stage_w = (stage_w == NSTAGE - 1) ? 0 : stage_w + 1;
    }
#undef ISSUE_COPY

    // ---- epilogue
    int tr = lane >> 2;
    int tc = (lane & 3) * 2;
    const float* be = bias + (size_t)e * NTOT;
#pragma unroll
    for (int nt = 0; nt < 4; nt++) {
        int col = n0 + warp_n * 32 + nt * 8 + tc;
        float bv0 = __ldg(be + col);
        float bv1 = __ldg(be + col + 1);
#pragma unroll
        for (int mt = 0; mt < 4; mt++) {
            int rowa = row0 + warp_m * 64 + mt * 16 + tr;
#pragma unroll
            for (int half = 0; half < 2; half++) {
                int row = rowa + half * 8;
                float v0 = acc[mt][nt][2 * half + 0] + bv0;
                float v1 = acc[mt][nt][2 * half + 1] + bv1;
                if (GATHER) {
                    v0 = 0.5f * v0 * (1.0f + erff(v0 * 0.70710678118654752f));
                    v1 = 0.5f * v1 * (1.0f + erff(v1 * 0.70710678118654752f));
                    *(uint32_t*)(g_Hf + (size_t)row * F_DIM + col) =
                        pack_h2(__float2half_rn(v0), __float2half_rn(v1));
                } else {
                    float w = g_roww[row];
                    if (w != 0.0f) {
                        int tok = g_rowtok[row];
                        float* dst = out + (size_t)tok * D_DIM + col;
                        REDADD2(dst, w * v0, w * v1);
                    }
                }
            }
        }
    }
}

// ---------------------------------------------------------------------------
// Launch
// ---------------------------------------------------------------------------
extern "C" void kernel_launch(void* const* d_in, const int* in_sizes, int n_in,
                              void* d_out, int out_size) {
    const float* x  = (const float*)d_in[0];
    const float* rw = (const float*)d_in[1];
    const float* rb = (const float*)d_in[2];
    const float* w1 = (const float*)d_in[3];
    const float* b1 = (const float*)d_in[4];
    const float* w2 = (const float*)d_in[5];
    const float* b2 = (const float*)d_in[6];
    float* out = (float*)d_out;

    static bool attr_done = false;
    if (!attr_done) {
        cudaFuncSetAttribute(moe_gemm<true, D_DIM, F_DIM>,
                             cudaFuncAttributeMaxDynamicSharedMemorySize, SM_TOTAL);
        cudaFuncSetAttribute(moe_gemm<false, F_DIM, D_DIM>,
                             cudaFuncAttributeMaxDynamicSharedMemorySize, SM_TOTAL);
        attr_done = true;
    }

    __half* w2f;
    cudaGetSymbolAddress((void**)&w2f, g_w2f);

    // prep: router(+x conv) | w1 conv | out zero | gated scatter — one launch
    prep_kernel<<<P_TOTAL, 256>>>(x, rw, rb, (const float4*)w1, out);

    // GEMM1: y==0 -> w2 conversion (overlapped); y in [1,ROWTILES] -> tiles
    int w2n4 = E_NUM * F_DIM * D_DIM / 4;
    moe_gemm<true, D_DIM, F_DIM>
        <<<dim3(F_DIM / BN, ROWTILES + 1), 256, SM_TOTAL>>>(
            b1, nullptr, (const float4*)w2, w2f, w2n4);
    moe_gemm<false, F_DIM, D_DIM>
        <<<dim3(D_DIM / BN, ROWTILES), 256, SM_TOTAL>>>(
            b2, out, nullptr, nullptr, 0);
}

// round 14
// speedup vs baseline: 1.0566x; 1.0566x over previous
#include <cuda_runtime.h>
#include <cuda_fp16.h>
#include <math.h>
#include <stdint.h>

// ---------------------------------------------------------------------------
// Problem constants
// ---------------------------------------------------------------------------
#define T_TOK 4096
#define D_DIM 1024
#define F_DIM 4096
#define E_NUM 8
#define K_TOP 2

#define BM 128
#define BN 128
#define BK 32
#define NSTAGE 5

#define CAPR (T_TOK * K_TOP + E_NUM * BM)   // 9216
#define ROWTILES (CAPR / BM)                // 72

// prep work partition (flat 1D grid, CTAs proportional to bytes moved)
#define P_ROUTER 512
#define P_XCONV  96
#define P_W1CONV 1280
#define P_ZERO   64
#define P_TOTAL  (P_ROUTER + P_XCONV + P_W1CONV + P_ZERO + 1)   // 1953

// SMEM stage layout (bytes, within one stage)
#define A_ROWB 80                            // 32 fp16 = 64B + 16B pad
#define SM_A    0
#define SM_B    (BM * A_ROWB)                // 10240
#define STAGEB  (SM_B + BK * 256)            // 18432
#define SM_TOTAL (STAGEB * NSTAGE)           // 92160  (x2 CTAs = 180KB < 228KB)

// ---------------------------------------------------------------------------
// PTX helpers
// ---------------------------------------------------------------------------
static __device__ __forceinline__ uint32_t smem_u32(const void* p) {
    uint32_t a;
    asm("{ .reg .u64 t; cvta.to.shared.u64 t, %1; cvt.u32.u64 %0, t; }" : "=r"(a) : "l"(p));
    return a;
}

#define CP16(dst, src) \
    asm volatile("cp.async.cg.shared.global [%0], [%1], 16;" :: "r"(dst), "l"(src))
#define CP_COMMIT() asm volatile("cp.async.commit_group;")
#define CP_WAIT3()  asm volatile("cp.async.wait_group 3;")

#define LDSMX4(R, addr) \
    asm volatile("ldmatrix.sync.aligned.m8n8.x4.shared.b16 {%0,%1,%2,%3}, [%4];" \
        : "=r"((R)[0]), "=r"((R)[1]), "=r"((R)[2]), "=r"((R)[3]) : "r"(addr))
#define LDSMX4T(R, addr) \
    asm volatile("ldmatrix.sync.aligned.m8n8.x4.trans.shared.b16 {%0,%1,%2,%3}, [%4];" \
        : "=r"((R)[0]), "=r"((R)[1]), "=r"((R)[2]), "=r"((R)[3]) : "r"(addr))

#define MMA16816(C, A, B) \
    asm volatile("mma.sync.aligned.m16n8k16.row.col.f32.f16.f16.f32 " \
        "{%0,%1,%2,%3}, {%4,%5,%6,%7}, {%8,%9}, {%0,%1,%2,%3};" \
        : "+f"((C)[0]), "+f"((C)[1]), "+f"((C)[2]), "+f"((C)[3]) \
        : "r"((A)[0]), "r"((A)[1]), "r"((A)[2]), "r"((A)[3]), "r"((B)[0]), "r"((B)[1]))

#define REDADD2(addr, v0, v1) \
    asm volatile("red.global.add.v2.f32 [%0], {%1, %2};" :: "l"(addr), "f"(v0), "f"(v1) : "memory")

static __device__ __forceinline__ uint32_t pack_h2(__half a, __half b) {
    return ((uint32_t)__half_as_ushort(b) << 16) | (uint32_t)__half_as_ushort(a);
}

static __device__ __forceinline__ uint32_t ld_acq(const uint32_t* p) {
    uint32_t v;
    asm volatile("ld.global.acquire.gpu.u32 %0, [%1];" : "=r"(v) : "l"(p));
    return v;
}

// wide fp32x8 -> fp16x8 convert (2x LDG.128, 1x STG.128)
static __device__ __forceinline__ void conv8(const float4* __restrict__ src,
                                             uint4* __restrict__ dst, int i) {
    float4 a = src[2 * i];
    float4 b = src[2 * i + 1];
    uint4 o;
    o.x = pack_h2(__float2half_rn(a.x), __float2half_rn(a.y));
    o.y = pack_h2(__float2half_rn(a.z), __float2half_rn(a.w));
    o.z = pack_h2(__float2half_rn(b.x), __float2half_rn(b.y));
    o.w = pack_h2(__float2half_rn(b.z), __float2half_rn(b.w));
    dst[i] = o;
}

// ---------------------------------------------------------------------------
// Scratch (static device globals)
// ---------------------------------------------------------------------------
__device__ __align__(16) __half g_xf[(size_t)T_TOK * D_DIM];
__device__ __align__(16) __half g_w1f[(size_t)E_NUM * D_DIM * F_DIM];
__device__ __align__(16) __half g_w2f[(size_t)E_NUM * F_DIM * D_DIM];
__device__ __align__(16) __half g_Hf[(size_t)CAPR * F_DIM];
__device__ int   g_rowtok[CAPR];
__device__ float g_roww[CAPR];
__device__ float g_tokw[T_TOK * K_TOP];
__device__ int   g_toke[T_TOK * K_TOP];
__device__ int   g_poff[E_NUM + 1];
__device__ int   g_npad;
__device__ uint32_t g_rtdone = 0;   // router-done counter (self-resetting)

// ---------------------------------------------------------------------------
// Fused prep kernel (flat grid, work-proportional partition):
//   [0, P_ROUTER)       router (coalesced, 1 warp/token)
//   [.., +P_XCONV)      x  -> fp16 (8 elems/thread/iter)
//   [.., +P_W1CONV)     w1 -> fp16 (8 elems/thread/iter)
//   [.., +P_ZERO)       zero out[]
//   last CTA            gated scatter (count -> offsets -> place)
// ---------------------------------------------------------------------------
__global__ void __launch_bounds__(256)
prep_kernel(const float* __restrict__ x,
            const float* __restrict__ rw,
            const float* __restrict__ rb,
            const float4* __restrict__ w1,
            float* __restrict__ out) {
    int cta = blockIdx.x;
    int tid = threadIdx.x;

    if (cta < P_ROUTER) {
        // ---- router (original coalesced pattern) ----
        int warp = cta * 8 + (tid >> 5);
        int lane = tid & 31;
        const float* xr = x + (size_t)warp * D_DIM;
        float acc[E_NUM];
#pragma unroll
        for (int e = 0; e < E_NUM; e++) acc[e] = 0.0f;
        for (int d = lane; d < D_DIM; d += 32) {
            float xv = xr[d];
            const float* w = rw + (size_t)d * E_NUM;
#pragma unroll
            for (int e = 0; e < E_NUM; e++) acc[e] += xv * w[e];
        }
#pragma unroll
        for (int off = 16; off; off >>= 1)
#pragma unroll
            for (int e = 0; e < E_NUM; e++)
                acc[e] += __shfl_down_sync(0xFFFFFFFFu, acc[e], off);
        if (lane == 0) {
            float l[E_NUM];
#pragma unroll
            for (int e = 0; e < E_NUM; e++) l[e] = acc[e] + rb[e];
            int i0 = 0;
#pragma unroll
            for (int e = 1; e < E_NUM; e++) if (l[e] > l[i0]) i0 = e;
            int i1 = -1;
#pragma unroll
            for (int e = 0; e < E_NUM; e++) {
                if (e == i0) continue;
                if (i1 < 0 || l[e] > l[i1]) i1 = e;
            }
            float w0 = 1.0f / (1.0f + expf(l[i1] - l[i0]));
            g_toke[warp * 2 + 0] = i0;
            g_toke[warp * 2 + 1] = i1;
            g_tokw[warp * 2 + 0] = w0;
            g_tokw[warp * 2 + 1] = 1.0f - w0;
        }
        __threadfence();
        __syncthreads();
        if (tid == 0) atomicAdd(&g_rtdone, 1u);
    } else if (cta < P_ROUTER + P_XCONV) {
        // ---- x -> fp16, wide ----
        const int n8 = T_TOK * D_DIM / 8;
        int stride = P_XCONV * 256;
        for (int i = (cta - P_ROUTER) * 256 + tid; i < n8; i += stride)
            conv8((const float4*)x, (uint4*)g_xf, i);
    } else if (cta < P_ROUTER + P_XCONV + P_W1CONV) {
        // ---- w1 -> fp16, wide ----
        const int n8 = E_NUM * D_DIM * F_DIM / 8;
        int stride = P_W1CONV * 256;
        for (int i = (cta - P_ROUTER - P_XCONV) * 256 + tid; i < n8; i += stride)
            conv8(w1, (uint4*)g_w1f, i);
    } else if (cta < P_ROUTER + P_XCONV + P_W1CONV + P_ZERO) {
        // ---- zero out[] ----
        float4* o4 = (float4*)out;
        const int n4 = T_TOK * D_DIM / 4;
        int stride = P_ZERO * 256;
        float4 z = make_float4(0.f, 0.f, 0.f, 0.f);
        for (int i = (cta - P_ROUTER - P_XCONV - P_W1CONV) * 256 + tid; i < n4; i += stride)
            o4[i] = z;
    } else {
        // ---- gated scatter CTA ----
        __shared__ int s_cnt[E_NUM];
        __shared__ int s_cur[E_NUM];
        if (tid < E_NUM) s_cnt[tid] = 0;
        if (tid == 0) {
            while (ld_acq(&g_rtdone) < P_ROUTER) __nanosleep(128);
        }
        __syncthreads();
        for (int i = tid; i < T_TOK * K_TOP; i += 256)
            atomicAdd(&s_cnt[g_toke[i]], 1);
        __syncthreads();
        if (tid == 0) {
            int off = 0;
            for (int e = 0; e < E_NUM; e++) {
                g_poff[e] = off;
                s_cur[e] = off;
                off += ((s_cnt[e] + BM - 1) / BM) * BM;
            }
            g_poff[E_NUM] = off;
            g_npad = off;
        }
        __syncthreads();
        for (int i = tid; i < CAPR; i += 256) {
            g_rowtok[i] = 0;
            g_roww[i] = 0.0f;
        }
        __syncthreads();
        for (int i = tid; i < T_TOK * K_TOP; i += 256) {
            int e = g_toke[i];
            int p = atomicAdd(&s_cur[e], 1);
            g_rowtok[p] = i >> 1;
            g_roww[p] = g_tokw[i];
        }
        __syncthreads();
        if (tid == 0) g_rtdone = 0;   // self-reset for next graph replay
    }
}

// ---------------------------------------------------------------------------
// fp16 HMMA GEMM (single product), BK=32, 5-stage cp.async pipeline,
// one barrier per k-chunk, chunk-wide B-fragment preload (R10 body).
// GEMM1 (GATHER): blockIdx.y==0 slice converts w2->fp16; epilogue GELU->g_Hf.
// GEMM2 (!GATHER): epilogue w*(acc+bias) accumulated into out[] (red.v2.f32).
// ---------------------------------------------------------------------------
template<bool GATHER, int KTOT, int NTOT>
__global__ void __launch_bounds__(256, 2)
moe_gemm(const float* __restrict__ bias, float* __restrict__ out,
         const float4* __restrict__ cvt_src, __half* __restrict__ cvt_dst, int cvt_n4) {
    int by = blockIdx.y;
    if (GATHER) {
        if (by == 0) {
            int stride = gridDim.x * blockDim.x;
            int base = blockIdx.x * blockDim.x + threadIdx.x;
            for (int i = base; i < cvt_n4; i += 4 * stride) {
#pragma unroll
                for (int u = 0; u < 4; u++) {
                    int j = i + u * stride;
                    if (j < cvt_n4) {
                        float4 v = cvt_src[j];
                        uint32_t w0 = pack_h2(__float2half_rn(v.x), __float2half_rn(v.y));
                        uint32_t w1 = pack_h2(__float2half_rn(v.z), __float2half_rn(v.w));
                        ((uint2*)cvt_dst)[j] = make_uint2(w0, w1);
                    }
                }
            }
            return;
        }
        by -= 1;
    }

    int row0 = by * BM;
    if (row0 >= g_npad) return;
    int e = 0;
    while (row0 >= g_poff[e + 1]) e++;
    int n0 = blockIdx.x * BN;

    extern __shared__ char smem[];
    uint32_t su = smem_u32(smem);

    int tid = threadIdx.x;
    int lane = tid & 31;
    int wid = tid >> 5;
    int warp_m = wid & 1;
    int warp_n = wid >> 1;

    const __half* a_g;
    {
        int r = tid >> 1;
        if (GATHER) {
            int tok = g_rowtok[row0 + r];
            a_g = g_xf + (size_t)tok * KTOT;
        } else {
            a_g = g_Hf + (size_t)(row0 + r) * KTOT;
        }
    }
    const __half* b_g = (GATHER ? g_w1f : g_w2f) + (size_t)e * KTOT * NTOT;

    int ar = tid >> 1;
    int ac = (tid & 1) * 2;
    uint32_t a_dst = su + ar * A_ROWB + ac * 16;
    int bkr = tid >> 3;
    int bc = (tid & 7) * 2;
    uint32_t b_dst0 = su + SM_B + bkr * 256 + ((bc * 16) ^ ((bkr & 7) << 4));
    uint32_t b_dst1 = su + SM_B + bkr * 256 + (((bc + 1) * 16) ^ ((bkr & 7) << 4));

    float acc[4][4][4];
#pragma unroll
    for (int mt = 0; mt < 4; mt++)
#pragma unroll
        for (int nt = 0; nt < 4; nt++)
#pragma unroll
            for (int q = 0; q < 4; q++) acc[mt][nt][q] = 0.0f;

    uint32_t a_lds = (uint32_t)((warp_m * 64 + (lane & 15)) * A_ROWB + ((lane >> 4) * 8) * 2);
    int krow_base = (lane & 7) + ((lane >> 3) & 1) * 8;
    int nb_base = (warp_n * 32 + ((lane >> 4) & 1) * 8) * 2;

    const int NK = KTOT / BK;

#define ISSUE_COPY(kc, sb_off)                                                      \
    do {                                                                            \
        int k0_ = (kc) * BK;                                                        \
        const __half* pa_ = a_g + k0_ + ac * 8;                                     \
        CP16((sb_off) + a_dst, pa_); CP16((sb_off) + a_dst + 16, pa_ + 8);          \
        const __half* pb_ = b_g + (size_t)(k0_ + bkr) * NTOT + n0 + bc * 8;         \
        CP16((sb_off) + b_dst0, pb_); CP16((sb_off) + b_dst1, pb_ + 8);             \
    } while (0)

    ISSUE_COPY(0, 0);
    CP_COMMIT();
    ISSUE_COPY(1, STAGEB);
    CP_COMMIT();
    ISSUE_COPY(2, 2 * STAGEB);
    CP_COMMIT();
    ISSUE_COPY(3, 3 * STAGEB);
    CP_COMMIT();

    int stage = 0;
    int stage_w = 4;
    for (int kc = 0; kc < NK; kc++) {
        CP_WAIT3();
        __syncthreads();
        if (kc + 4 < NK) ISSUE_COPY(kc + 4, (uint32_t)stage_w * STAGEB);
        CP_COMMIT();

        uint32_t sb = su + (uint32_t)stage * STAGEB;

        uint32_t b_r[2][4][2];
#pragma unroll
        for (int ks = 0; ks < 2; ks++) {
#pragma unroll
            for (int pt = 0; pt < 2; pt++) {
                int krow = ks * 16 + krow_base;
                int nb = nb_base + pt * 32;
                uint32_t bd = sb + SM_B + krow * 256 + (nb ^ ((krow & 7) << 4));
                uint32_t r[4];
                LDSMX4T(r, bd);
                b_r[ks][2 * pt][0] = r[0]; b_r[ks][2 * pt][1] = r[1];
                b_r[ks][2 * pt + 1][0] = r[2]; b_r[ks][2 * pt + 1][1] = r[3];
            }
        }
#pragma unroll
        for (int ks = 0; ks < 2; ks++) {
            uint32_t a_r[4][4];
#pragma unroll
            for (int mt = 0; mt < 4; mt++) {
                uint32_t ad = sb + a_lds + (uint32_t)(mt * 16 * A_ROWB + ks * 32);
                LDSMX4(a_r[mt], ad);
            }
#pragma unroll
            for (int mt = 0; mt < 4; mt++)
#pragma unroll
                for (int nt = 0; nt < 4; nt++)
                    MMA16816(acc[mt][nt], a_r[mt], b_r[ks][nt]);
        }
        stage = (stage == NSTAGE - 1) ? 0 : stage + 1;
        stage_w = (stage_w == NSTAGE - 1) ? 0 : stage_w + 1;
    }
#undef ISSUE_COPY

    // ---- epilogue
    int tr = lane >> 2;
    int tc = (lane & 3) * 2;
    const float* be = bias + (size_t)e * NTOT;
#pragma unroll
    for (int nt = 0; nt < 4; nt++) {
        int col = n0 + warp_n * 32 + nt * 8 + tc;
        float bv0 = __ldg(be + col);
        float bv1 = __ldg(be + col + 1);
#pragma unroll
        for (int mt = 0; mt < 4; mt++) {
            int rowa = row0 + warp_m * 64 + mt * 16 + tr;
#pragma unroll
            for (int half = 0; half < 2; half++) {
                int row = rowa + half * 8;
                float v0 = acc[mt][nt][2 * half + 0] + bv0;
                float v1 = acc[mt][nt][2 * half + 1] + bv1;
                if (GATHER) {
                    v0 = 0.5f * v0 * (1.0f + erff(v0 * 0.70710678118654752f));
                    v1 = 0.5f * v1 * (1.0f + erff(v1 * 0.70710678118654752f));
                    *(uint32_t*)(g_Hf + (size_t)row * F_DIM + col) =
                        pack_h2(__float2half_rn(v0), __float2half_rn(v1));
                } else {
                    float w = g_roww[row];
                    if (w != 0.0f) {
                        int tok = g_rowtok[row];
                        float* dst = out + (size_t)tok * D_DIM + col;
                        REDADD2(dst, w * v0, w * v1);
                    }
                }
            }
        }
    }
}

// ---------------------------------------------------------------------------
// Launch
// ---------------------------------------------------------------------------
extern "C" void kernel_launch(void* const* d_in, const int* in_sizes, int n_in,
                              void* d_out, int out_size) {
    const float* x  = (const float*)d_in[0];
    const float* rw = (const float*)d_in[1];
    const float* rb = (const float*)d_in[2];
    const float* w1 = (const float*)d_in[3];
    const float* b1 = (const float*)d_in[4];
    const float* w2 = (const float*)d_in[5];
    const float* b2 = (const float*)d_in[6];
    float* out = (float*)d_out;

    static bool attr_done = false;
    if (!attr_done) {
        cudaFuncSetAttribute(moe_gemm<true, D_DIM, F_DIM>,
                             cudaFuncAttributeMaxDynamicSharedMemorySize, SM_TOTAL);
        cudaFuncSetAttribute(moe_gemm<false, F_DIM, D_DIM>,
                             cudaFuncAttributeMaxDynamicSharedMemorySize, SM_TOTAL);
        attr_done = true;
    }

    __half* w2f;
    cudaGetSymbolAddress((void**)&w2f, g_w2f);

    // prep: router | x conv | w1 conv | out zero | gated scatter — one launch
    prep_kernel<<<P_TOTAL, 256>>>(x, rw, rb, (const float4*)w1, out);

    // GEMM1: y==0 -> w2 conversion (overlapped); y in [1,ROWTILES] -> tiles
    int w2n4 = E_NUM * F_DIM * D_DIM / 4;
    moe_gemm<true, D_DIM, F_DIM>
        <<<dim3(F_DIM / BN, ROWTILES + 1), 256, SM_TOTAL>>>(
            b1, nullptr, (const float4*)w2, w2f, w2n4);
    moe_gemm<false, F_DIM, D_DIM>
        <<<dim3(D_DIM / BN, ROWTILES), 256, SM_TOTAL>>>(
            b2, out, nullptr, nullptr, 0);
}

// round 15
// speedup vs baseline: 1.0645x; 1.0075x over previous
#include <cuda_runtime.h>
#include <cuda_fp16.h>
#include <math.h>
#include <stdint.h>

// ---------------------------------------------------------------------------
// Problem constants
// ---------------------------------------------------------------------------
#define T_TOK 4096
#define D_DIM 1024
#define F_DIM 4096
#define E_NUM 8
#define K_TOP 2

#define BM 128
#define BN 128
#define BK 32
#define NSTAGE 5

#define CAPR (T_TOK * K_TOP + E_NUM * BM)   // 9216
#define ROWTILES (CAPR / BM)                // 72

// prep work partition (flat 1D grid)
#define P_ROUTER 512
#define P_W1CONV 1376
#define P_ZERO   64
#define P_TOTAL  (P_ROUTER + P_W1CONV + P_ZERO + 1)   // 1953

// SMEM stage layout (bytes, within one stage)
#define A_ROWB 80                            // 32 fp16 = 64B + 16B pad
#define SM_A    0
#define SM_B    (BM * A_ROWB)                // 10240
#define STAGEB  (SM_B + BK * 256)            // 18432
#define SM_TOTAL (STAGEB * NSTAGE)           // 92160  (x2 CTAs = 180KB < 228KB)

// ---------------------------------------------------------------------------
// PTX helpers
// ---------------------------------------------------------------------------
static __device__ __forceinline__ uint32_t smem_u32(const void* p) {
    uint32_t a;
    asm("{ .reg .u64 t; cvta.to.shared.u64 t, %1; cvt.u32.u64 %0, t; }" : "=r"(a) : "l"(p));
    return a;
}

#define CP16(dst, src) \
    asm volatile("cp.async.cg.shared.global [%0], [%1], 16;" :: "r"(dst), "l"(src))
#define CP_COMMIT() asm volatile("cp.async.commit_group;")
#define CP_WAIT3()  asm volatile("cp.async.wait_group 3;")

#define LDSMX4(R, addr) \
    asm volatile("ldmatrix.sync.aligned.m8n8.x4.shared.b16 {%0,%1,%2,%3}, [%4];" \
        : "=r"((R)[0]), "=r"((R)[1]), "=r"((R)[2]), "=r"((R)[3]) : "r"(addr))
#define LDSMX4T(R, addr) \
    asm volatile("ldmatrix.sync.aligned.m8n8.x4.trans.shared.b16 {%0,%1,%2,%3}, [%4];" \
        : "=r"((R)[0]), "=r"((R)[1]), "=r"((R)[2]), "=r"((R)[3]) : "r"(addr))

#define MMA16816(C, A, B) \
    asm volatile("mma.sync.aligned.m16n8k16.row.col.f32.f16.f16.f32 " \
        "{%0,%1,%2,%3}, {%4,%5,%6,%7}, {%8,%9}, {%0,%1,%2,%3};" \
        : "+f"((C)[0]), "+f"((C)[1]), "+f"((C)[2]), "+f"((C)[3]) \
        : "r"((A)[0]), "r"((A)[1]), "r"((A)[2]), "r"((A)[3]), "r"((B)[0]), "r"((B)[1]))

#define REDADD2(addr, v0, v1) \
    asm volatile("red.global.add.v2.f32 [%0], {%1, %2};" :: "l"(addr), "f"(v0), "f"(v1) : "memory")

static __device__ __forceinline__ uint32_t pack_h2(__half a, __half b) {
    return ((uint32_t)__half_as_ushort(b) << 16) | (uint32_t)__half_as_ushort(a);
}

static __device__ __forceinline__ uint32_t ld_acq(const uint32_t* p) {
    uint32_t v;
    asm volatile("ld.global.acquire.gpu.u32 %0, [%1];" : "=r"(v) : "l"(p));
    return v;
}

// wide fp32x8 -> fp16x8 convert (2x LDG.128, 1x STG.128)
static __device__ __forceinline__ void conv8(const float4* __restrict__ src,
                                             uint4* __restrict__ dst, int i) {
    float4 a = src[2 * i];
    float4 b = src[2 * i + 1];
    uint4 o;
    o.x = pack_h2(__float2half_rn(a.x), __float2half_rn(a.y));
    o.y = pack_h2(__float2half_rn(a.z), __float2half_rn(a.w));
    o.z = pack_h2(__float2half_rn(b.x), __float2half_rn(b.y));
    o.w = pack_h2(__float2half_rn(b.z), __float2half_rn(b.w));
    dst[i] = o;
}

// ---------------------------------------------------------------------------
// Scratch (static device globals)
// ---------------------------------------------------------------------------
__device__ __align__(16) __half g_xf[(size_t)T_TOK * D_DIM];
__device__ __align__(16) __half g_w1f[(size_t)E_NUM * D_DIM * F_DIM];
__device__ __align__(16) __half g_w2f[(size_t)E_NUM * F_DIM * D_DIM];
__device__ __align__(16) __half g_Hf[(size_t)CAPR * F_DIM];
__device__ int   g_rowtok[CAPR];
__device__ float g_roww[CAPR];
__device__ float g_tokw[T_TOK * K_TOP];
__device__ int   g_toke[T_TOK * K_TOP];
__device__ int   g_poff[E_NUM + 1];
__device__ int   g_npad;
__device__ uint32_t g_rtdone = 0;   // router-done counter (self-resetting)

// ---------------------------------------------------------------------------
// Fused prep kernel (flat grid):
//   [0, P_ROUTER)       router: float4 x / rw loads; writes g_xf as byproduct
//   [.., +P_W1CONV)     w1 -> fp16 (8 elems/thread/iter)
//   [.., +P_ZERO)       zero out[]
//   last CTA            gated scatter
// ---------------------------------------------------------------------------
__global__ void __launch_bounds__(256)
prep_kernel(const float* __restrict__ x,
            const float* __restrict__ rw,
            const float* __restrict__ rb,
            const float4* __restrict__ w1,
            float* __restrict__ out) {
    int cta = blockIdx.x;
    int tid = threadIdx.x;

    if (cta < P_ROUTER) {
        // ---- router + x->fp16 byproduct (all loads float4, coalesced) ----
        int warp = cta * 8 + (tid >> 5);
        int lane = tid & 31;
        const float4* xr = (const float4*)(x + (size_t)warp * D_DIM);
        uint2* xo = (uint2*)(g_xf + (size_t)warp * D_DIM);
        const float4* rw4 = (const float4*)rw;
        float acc[E_NUM];
#pragma unroll
        for (int e = 0; e < E_NUM; e++) acc[e] = 0.0f;
#pragma unroll
        for (int i = 0; i < D_DIM / 128; i++) {
            int q = lane + 32 * i;                   // float4 index; d0 = 4q
            float4 xv = xr[q];
            xo[q] = make_uint2(pack_h2(__float2half_rn(xv.x), __float2half_rn(xv.y)),
                               pack_h2(__float2half_rn(xv.z), __float2half_rn(xv.w)));
            float xs[4] = {xv.x, xv.y, xv.z, xv.w};
#pragma unroll
            for (int j = 0; j < 4; j++) {
                float4 wa = rw4[(size_t)(4 * q + j) * 2];
                float4 wb = rw4[(size_t)(4 * q + j) * 2 + 1];
                acc[0] += xs[j] * wa.x; acc[1] += xs[j] * wa.y;
                acc[2] += xs[j] * wa.z; acc[3] += xs[j] * wa.w;
                acc[4] += xs[j] * wb.x; acc[5] += xs[j] * wb.y;
                acc[6] += xs[j] * wb.z; acc[7] += xs[j] * wb.w;
            }
        }
#pragma unroll
        for (int off = 16; off; off >>= 1)
#pragma unroll
            for (int e = 0; e < E_NUM; e++)
                acc[e] += __shfl_down_sync(0xFFFFFFFFu, acc[e], off);
        if (lane == 0) {
            float l[E_NUM];
#pragma unroll
            for (int e = 0; e < E_NUM; e++) l[e] = acc[e] + rb[e];
            int i0 = 0;
#pragma unroll
            for (int e = 1; e < E_NUM; e++) if (l[e] > l[i0]) i0 = e;
            int i1 = -1;
#pragma unroll
            for (int e = 0; e < E_NUM; e++) {
                if (e == i0) continue;
                if (i1 < 0 || l[e] > l[i1]) i1 = e;
            }
            float w0 = 1.0f / (1.0f + expf(l[i1] - l[i0]));
            g_toke[warp * 2 + 0] = i0;
            g_toke[warp * 2 + 1] = i1;
            g_tokw[warp * 2 + 0] = w0;
            g_tokw[warp * 2 + 1] = 1.0f - w0;
        }
        __threadfence();
        __syncthreads();
        if (tid == 0) atomicAdd(&g_rtdone, 1u);
    } else if (cta < P_ROUTER + P_W1CONV) {
        // ---- w1 -> fp16, wide ----
        const int n8 = E_NUM * D_DIM * F_DIM / 8;
        int stride = P_W1CONV * 256;
        for (int i = (cta - P_ROUTER) * 256 + tid; i < n8; i += stride)
            conv8(w1, (uint4*)g_w1f, i);
    } else if (cta < P_ROUTER + P_W1CONV + P_ZERO) {
        // ---- zero out[] ----
        float4* o4 = (float4*)out;
        const int n4 = T_TOK * D_DIM / 4;
        int stride = P_ZERO * 256;
        float4 z = make_float4(0.f, 0.f, 0.f, 0.f);
        for (int i = (cta - P_ROUTER - P_W1CONV) * 256 + tid; i < n4; i += stride)
            o4[i] = z;
    } else {
        // ---- gated scatter CTA ----
        __shared__ int s_cnt[E_NUM];
        __shared__ int s_cur[E_NUM];
        if (tid < E_NUM) s_cnt[tid] = 0;
        if (tid == 0) {
            while (ld_acq(&g_rtdone) < P_ROUTER) __nanosleep(128);
        }
        __syncthreads();
        for (int i = tid; i < T_TOK * K_TOP; i += 256)
            atomicAdd(&s_cnt[g_toke[i]], 1);
        __syncthreads();
        if (tid == 0) {
            int off = 0;
            for (int e = 0; e < E_NUM; e++) {
                g_poff[e] = off;
                s_cur[e] = off;
                off += ((s_cnt[e] + BM - 1) / BM) * BM;
            }
            g_poff[E_NUM] = off;
            g_npad = off;
        }
        __syncthreads();
        for (int i = tid; i < CAPR; i += 256) {
            g_rowtok[i] = 0;
            g_roww[i] = 0.0f;
        }
        __syncthreads();
        for (int i = tid; i < T_TOK * K_TOP; i += 256) {
            int e = g_toke[i];
            int p = atomicAdd(&s_cur[e], 1);
            g_rowtok[p] = i >> 1;
            g_roww[p] = g_tokw[i];
        }
        __syncthreads();
        if (tid == 0) g_rtdone = 0;   // self-reset for next graph replay
    }
}

// ---------------------------------------------------------------------------
// fp16 HMMA GEMM (single product), BK=32, 5-stage cp.async pipeline,
// one barrier per k-chunk, chunk-wide B-fragment preload (R10 body).
// GEMM1 (GATHER): blockIdx.y==0 slice converts w2->fp16; epilogue GELU->g_Hf.
// GEMM2 (!GATHER): epilogue w*(acc+bias) accumulated into out[] (red.v2.f32).
// ---------------------------------------------------------------------------
template<bool GATHER, int KTOT, int NTOT>
__global__ void __launch_bounds__(256, 2)
moe_gemm(const float* __restrict__ bias, float* __restrict__ out,
         const float4* __restrict__ cvt_src, __half* __restrict__ cvt_dst, int cvt_n4) {
    int by = blockIdx.y;
    if (GATHER) {
        if (by == 0) {
            int stride = gridDim.x * blockDim.x;
            int base = blockIdx.x * blockDim.x + threadIdx.x;
            for (int i = base; i < cvt_n4; i += 4 * stride) {
#pragma unroll
                for (int u = 0; u < 4; u++) {
                    int j = i + u * stride;
                    if (j < cvt_n4) {
                        float4 v = cvt_src[j];
                        uint32_t w0 = pack_h2(__float2half_rn(v.x), __float2half_rn(v.y));
                        uint32_t w1 = pack_h2(__float2half_rn(v.z), __float2half_rn(v.w));
                        ((uint2*)cvt_dst)[j] = make_uint2(w0, w1);
                    }
                }
            }
            return;
        }
        by -= 1;
    }

    int row0 = by * BM;
    if (row0 >= g_npad) return;
    int e = 0;
    while (row0 >= g_poff[e + 1]) e++;
    int n0 = blockIdx.x * BN;

    extern __shared__ char smem[];
    uint32_t su = smem_u32(smem);

    int tid = threadIdx.x;
    int lane = tid & 31;
    int wid = tid >> 5;
    int warp_m = wid & 1;
    int warp_n = wid >> 1;

    const __half* a_g;
    {
        int r = tid >> 1;
        if (GATHER) {
            int tok = g_rowtok[row0 + r];
            a_g = g_xf + (size_t)tok * KTOT;
        } else {
            a_g = g_Hf + (size_t)(row0 + r) * KTOT;
        }
    }
    const __half* b_g = (GATHER ? g_w1f : g_w2f) + (size_t)e * KTOT * NTOT;

    int ar = tid >> 1;
    int ac = (tid & 1) * 2;
    uint32_t a_dst = su + ar * A_ROWB + ac * 16;
    int bkr = tid >> 3;
    int bc = (tid & 7) * 2;
    uint32_t b_dst0 = su + SM_B + bkr * 256 + ((bc * 16) ^ ((bkr & 7) << 4));
    uint32_t b_dst1 = su + SM_B + bkr * 256 + (((bc + 1) * 16) ^ ((bkr & 7) << 4));

    float acc[4][4][4];
#pragma unroll
    for (int mt = 0; mt < 4; mt++)
#pragma unroll
        for (int nt = 0; nt < 4; nt++)
#pragma unroll
            for (int q = 0; q < 4; q++) acc[mt][nt][q] = 0.0f;

    uint32_t a_lds = (uint32_t)((warp_m * 64 + (lane & 15)) * A_ROWB + ((lane >> 4) * 8) * 2);
    int krow_base = (lane & 7) + ((lane >> 3) & 1) * 8;
    int nb_base = (warp_n * 32 + ((lane >> 4) & 1) * 8) * 2;

    const int NK = KTOT / BK;

#define ISSUE_COPY(kc, sb_off)                                                      \
    do {                                                                            \
        int k0_ = (kc) * BK;                                                        \
        const __half* pa_ = a_g + k0_ + ac * 8;                                     \
        CP16((sb_off) + a_dst, pa_); CP16((sb_off) + a_dst + 16, pa_ + 8);          \
        const __half* pb_ = b_g + (size_t)(k0_ + bkr) * NTOT + n0 + bc * 8;         \
        CP16((sb_off) + b_dst0, pb_); CP16((sb_off) + b_dst1, pb_ + 8);             \
    } while (0)

    ISSUE_COPY(0, 0);
    CP_COMMIT();
    ISSUE_COPY(1, STAGEB);
    CP_COMMIT();
    ISSUE_COPY(2, 2 * STAGEB);
    CP_COMMIT();
    ISSUE_COPY(3, 3 * STAGEB);
    CP_COMMIT();

    int stage = 0;
    int stage_w = 4;
    for (int kc = 0; kc < NK; kc++) {
        CP_WAIT3();
        __syncthreads();
        if (kc + 4 < NK) ISSUE_COPY(kc + 4, (uint32_t)stage_w * STAGEB);
        CP_COMMIT();

        uint32_t sb = su + (uint32_t)stage * STAGEB;

        uint32_t b_r[2][4][2];
#pragma unroll
        for (int ks = 0; ks < 2; ks++) {
#pragma unroll
            for (int pt = 0; pt < 2; pt++) {
                int krow = ks * 16 + krow_base;
                int nb = nb_base + pt * 32;
                uint32_t bd = sb + SM_B + krow * 256 + (nb ^ ((krow & 7) << 4));
                uint32_t r[4];
                LDSMX4T(r, bd);
                b_r[ks][2 * pt][0] = r[0]; b_r[ks][2 * pt][1] = r[1];
                b_r[ks][2 * pt + 1][0] = r[2]; b_r[ks][2 * pt + 1][1] = r[3];
            }
        }
#pragma unroll
        for (int ks = 0; ks < 2; ks++) {
            uint32_t a_r[4][4];
#pragma unroll
            for (int mt = 0; mt < 4; mt++) {
                uint32_t ad = sb + a_lds + (uint32_t)(mt * 16 * A_ROWB + ks * 32);
                LDSMX4(a_r[mt], ad);
            }
#pragma unroll
            for (int mt = 0; mt < 4; mt++)
#pragma unroll
                for (int nt = 0; nt < 4; nt++)
                    MMA16816(acc[mt][nt], a_r[mt], b_r[ks][nt]);
        }
        stage = (stage == NSTAGE - 1) ? 0 : stage + 1;
        stage_w = (stage_w == NSTAGE - 1) ? 0 : stage_w + 1;
    }
#undef ISSUE_COPY

    // ---- epilogue
    int tr = lane >> 2;
    int tc = (lane & 3) * 2;
    const float* be = bias + (size_t)e * NTOT;
#pragma unroll
    for (int nt = 0; nt < 4; nt++) {
        int col = n0 + warp_n * 32 + nt * 8 + tc;
        float bv0 = __ldg(be + col);
        float bv1 = __ldg(be + col + 1);
#pragma unroll
        for (int mt = 0; mt < 4; mt++) {
            int rowa = row0 + warp_m * 64 + mt * 16 + tr;
#pragma unroll
            for (int half = 0; half < 2; half++) {
                int row = rowa + half * 8;
                float v0 = acc[mt][nt][2 * half + 0] + bv0;
                float v1 = acc[mt][nt][2 * half + 1] + bv1;
                if (GATHER) {
                    v0 = 0.5f * v0 * (1.0f + erff(v0 * 0.70710678118654752f));
                    v1 = 0.5f * v1 * (1.0f + erff(v1 * 0.70710678118654752f));
                    *(uint32_t*)(g_Hf + (size_t)row * F_DIM + col) =
                        pack_h2(__float2half_rn(v0), __float2half_rn(v1));
                } else {
                    float w = g_roww[row];
                    if (w != 0.0f) {
                        int tok = g_rowtok[row];
                        float* dst = out + (size_t)tok * D_DIM + col;
                        REDADD2(dst, w * v0, w * v1);
                    }
                }
            }
        }
    }
}

// ---------------------------------------------------------------------------
// Launch
// ---------------------------------------------------------------------------
extern "C" void kernel_launch(void* const* d_in, const int* in_sizes, int n_in,
                              void* d_out, int out_size) {
    const float* x  = (const float*)d_in[0];
    const float* rw = (const float*)d_in[1];
    const float* rb = (const float*)d_in[2];
    const float* w1 = (const float*)d_in[3];
    const float* b1 = (const float*)d_in[4];
    const float* w2 = (const float*)d_in[5];
    const float* b2 = (const float*)d_in[6];
    float* out = (float*)d_out;

    static bool attr_done = false;
    if (!attr_done) {
        cudaFuncSetAttribute(moe_gemm<true, D_DIM, F_DIM>,
                             cudaFuncAttributeMaxDynamicSharedMemorySize, SM_TOTAL);
        cudaFuncSetAttribute(moe_gemm<false, F_DIM, D_DIM>,
                             cudaFuncAttributeMaxDynamicSharedMemorySize, SM_TOTAL);
        attr_done = true;
    }

    __half* w2f;
    cudaGetSymbolAddress((void**)&w2f, g_w2f);

    // prep: router(+x conv byproduct) | w1 conv | out zero | gated scatter
    prep_kernel<<<P_TOTAL, 256>>>(x, rw, rb, (const float4*)w1, out);

    // GEMM1: y==0 -> w2 conversion (overlapped); y in [1,ROWTILES] -> tiles
    int w2n4 = E_NUM * F_DIM * D_DIM / 4;
    moe_gemm<true, D_DIM, F_DIM>
        <<<dim3(F_DIM / BN, ROWTILES + 1), 256, SM_TOTAL>>>(
            b1, nullptr, (const float4*)w2, w2f, w2n4);
    moe_gemm<false, F_DIM, D_DIM>
        <<<dim3(D_DIM / BN, ROWTILES), 256, SM_TOTAL>>>(
            b2, out, nullptr, nullptr, 0);
}